// round 5
// baseline (speedup 1.0000x reference)
#include <cuda_runtime.h>

// FPN Pooler: multi-level ROIAlign via separable interpolation.
// Phase 1: coalesced row loads + warp shuffles -> x-interpolated samples X[r][ix] (smem, 6KB/warp)
// Phase 2: y-interpolation of bins from X-buffer (8 LDS + 8 FMA per bin).
// feats NCHW f32: f0 [2,256,200,200], f1 [2,256,100,100], f2 [2,256,50,50], f3 [2,256,25,25]
// boxes [1000,4], img_ids [1000] -> out [1000,256,7,7] f32

#define P 14          // OUT*SR samples per axis
#define MAXR 100      // max window rows (roi_h <= 100 at level 0)
#define XSTRIDE 15    // X-buffer row stride (14 + 1 pad)
#define NWARP 8
#define BLOCK 256
#define CPB 64        // channels per block -> 4 blocks per box
#define CH_PER_WARP 8 // CPB / NWARP

__global__ __launch_bounds__(BLOCK) void pooler_kernel(
    const float* __restrict__ f0, const float* __restrict__ f1,
    const float* __restrict__ f2, const float* __restrict__ f3,
    const float* __restrict__ boxes, const int* __restrict__ img_ids,
    float* __restrict__ out)
{
    const int bx   = blockIdx.x;
    const int n    = bx >> 2;
    const int cq   = (bx & 3) * CPB;
    const int tid  = threadIdx.x;
    const int warp = tid >> 5, lane = tid & 31;

    __shared__ float s_X[NWARP][MAXR * XSTRIDE];     // 48000 B
    __shared__ int   s_rx0[P], s_rx1[P], s_ry0[P], s_ry1[P];
    __shared__ float s_ax0[P], s_ax1[P], s_ay0[P], s_ay1[P];

    // ---- per-box scalars (redundant per thread) ----
    const float bx1 = boxes[4*n+0], by1 = boxes[4*n+1];
    const float bx2 = boxes[4*n+2], by2 = boxes[4*n+3];
    const float sq  = sqrtf((bx2 - bx1) * (by2 - by1));
    float lf = floorf(4.0f + log2f(sq / 224.0f + 1e-6f));
    lf = fminf(fmaxf(lf, 2.0f), 5.0f);
    const int lvl = (int)lf - 2;

    int H, W; float scale; const float* fp;
    switch (lvl) {
        case 0:  H = 200; W = 200; scale = 0.25f;    fp = f0; break;
        case 1:  H = 100; W = 100; scale = 0.125f;   fp = f1; break;
        case 2:  H = 50;  W = 50;  scale = 0.0625f;  fp = f2; break;
        default: H = 25;  W = 25;  scale = 0.03125f; fp = f3; break;
    }
    const int HW  = H * W;
    const int img = __ldg(img_ids + n);
    const float* gbase = fp + (size_t)img * 256 * HW;

    const float rx1 = bx1 * scale, ry1 = by1 * scale;
    const float roi_w = fmaxf(bx2 * scale - rx1, 1.0f);
    const float roi_h = fmaxf(by2 * scale - ry1, 1.0f);
    const float bw = roi_w * (1.0f / 7.0f);
    const float bh = roi_h * (1.0f / 7.0f);

    // ---- axis tables: x by threads 0..13, y by threads 16..29 ----
    if (tid < P) {
        const int i = tid, p = i >> 1, r = i & 1;
        const float xg = rx1 + (float)p * bw + ((float)r + 0.5f) * bw * 0.5f;
        const float vx = (xg >= -1.0f && xg <= (float)W) ? 1.0f : 0.0f;
        float x = fminf(fmaxf(xg, 0.0f), (float)(W - 1));
        const int x0 = (int)x;
        s_rx0[i] = x0;
        s_rx1[i] = min(x0 + 1, W - 1);
        const float lx = x - (float)x0;
        s_ax0[i] = vx * (1.0f - lx);   // fold validity-x
        s_ax1[i] = vx * lx;
    } else if (tid >= 16 && tid < 16 + P) {
        const int i = tid - 16, p = i >> 1, r = i & 1;
        const float yg = ry1 + (float)p * bh + ((float)r + 0.5f) * bh * 0.5f;
        const float vy = (yg >= -1.0f && yg <= (float)H) ? 0.25f : 0.0f;   // fold 0.25 mean
        float y = fminf(fmaxf(yg, 0.0f), (float)(H - 1));
        const int y0 = (int)y;
        s_ry0[i] = y0;
        s_ry1[i] = min(y0 + 1, H - 1);
        const float ly = y - (float)y0;
        s_ay0[i] = vy * (1.0f - ly);   // fold validity-y and 0.25
        s_ay1[i] = vy * ly;
    }
    __syncthreads();

    const int clo = s_rx0[0],  rlo = s_ry0[0];
    const int nc  = s_rx1[P-1] - clo + 1;
    const int nr  = s_ry1[P-1] - rlo + 1;
    const int nseg = (nc + 31) >> 5;

    // ---- x-lane role (lanes 0..13; others get harmless values) ----
    const int xl  = (lane < P) ? lane : 0;
    const int xw0 = s_rx0[xl] - clo;      // window-relative, 0..nc-1
    const int xw1 = s_rx1[xl] - clo;
    const float fx0 = s_ax0[xl];
    const float fx1 = s_ax1[xl];

    // ---- bin roles: bin s=0 -> lane, s=1 -> lane+32 (valid lane<17) ----
    int   oyA0[2], oyA1[2], oyB0[2], oyB1[2], ixA[2], ixB[2];
    float ayA0[2], ayA1[2], ayB0[2], ayB1[2];
    #pragma unroll
    for (int s = 0; s < 2; ++s) {
        const int bin = min(lane + 32 * s, 48);
        const int ph = bin / 7, pw = bin - ph * 7;
        const int iyA = 2*ph, iyB = iyA + 1;
        ixA[s] = 2*pw; ixB[s] = 2*pw + 1;
        oyA0[s] = (s_ry0[iyA] - rlo) * XSTRIDE;
        oyA1[s] = (s_ry1[iyA] - rlo) * XSTRIDE;
        oyB0[s] = (s_ry0[iyB] - rlo) * XSTRIDE;
        oyB1[s] = (s_ry1[iyB] - rlo) * XSTRIDE;
        ayA0[s] = s_ay0[iyA]; ayA1[s] = s_ay1[iyA];
        ayB0[s] = s_ay0[iyB]; ayB1[s] = s_ay1[iyB];
    }

    // ---- main loop: warp-autonomous per channel ----
    float* xb = s_X[warp];
    const int c0 = cq + warp * CH_PER_WARP;
    const float* gwin = gbase + (size_t)c0 * HW + rlo * W + clo;
    float* outp = out + (size_t)n * 12544 + (size_t)c0 * 49;

    for (int it = 0; it < CH_PER_WARP; ++it) {
        const float* gp = gwin + (size_t)it * HW;

        // phase 1: x-interpolate each window row
        #pragma unroll 2
        for (int r = 0; r < nr; ++r) {
            const float* rp = gp + r * W;
            float Xv = 0.0f;
            for (int seg = 0; seg < nseg; ++seg) {
                const int c = (seg << 5) | lane;
                float v = 0.0f;
                if (c < nc) v = __ldg(rp + c);
                const float sh0 = __shfl_sync(0xffffffffu, v, xw0);  // wraps mod 32
                const float sh1 = __shfl_sync(0xffffffffu, v, xw1);
                if ((xw0 >> 5) == seg) Xv = fmaf(fx0, sh0, Xv);
                if ((xw1 >> 5) == seg) Xv = fmaf(fx1, sh1, Xv);
            }
            if (lane < P) xb[r * XSTRIDE + lane] = Xv;
        }
        __syncwarp();

        // phase 2: y-interpolate bins from X-buffer
        #pragma unroll
        for (int s = 0; s < 2; ++s) {
            const float t00 = xb[oyA0[s] + ixA[s]] + xb[oyA0[s] + ixB[s]];
            const float t01 = xb[oyA1[s] + ixA[s]] + xb[oyA1[s] + ixB[s]];
            const float t10 = xb[oyB0[s] + ixA[s]] + xb[oyB0[s] + ixB[s]];
            const float t11 = xb[oyB1[s] + ixA[s]] + xb[oyB1[s] + ixB[s]];
            const float acc = ayA0[s] * t00 + ayA1[s] * t01
                            + ayB0[s] * t10 + ayB1[s] * t11;
            const int bin = lane + 32 * s;
            if (bin < 49) outp[bin] = acc;
        }
        outp += 49;
        __syncwarp();   // phase-2 reads done before next channel overwrites xb
    }
}

extern "C" void kernel_launch(void* const* d_in, const int* in_sizes, int n_in,
                              void* d_out, int out_size)
{
    const float* f0    = (const float*)d_in[0];
    const float* f1    = (const float*)d_in[1];
    const float* f2    = (const float*)d_in[2];
    const float* f3    = (const float*)d_in[3];
    const float* boxes = (const float*)d_in[4];
    const int*   imgs  = (const int*)d_in[5];
    float* out = (float*)d_out;

    const int N = in_sizes[4] / 4;   // 1000 boxes
    pooler_kernel<<<N * 4, BLOCK>>>(f0, f1, f2, f3, boxes, imgs, out);
}

// round 6
// speedup vs baseline: 2.5379x; 2.5379x over previous
#include <cuda_runtime.h>

// FPN Pooler: multi-level ROIAlign, direct scattered-gather (R2 structure),
// with fixed-bin-per-thread geometry hoisting and 2-channel ILP.
// feats NCHW f32: f0 [2,256,200,200], f1 [2,256,100,100], f2 [2,256,50,50], f3 [2,256,25,25]
// boxes [1000,4], img_ids [1000] -> out [1000,256,7,7] f32

#define P 14           // OUT*SR samples per axis
#define BLOCK 224      // 7 warps; 196 active threads (196 = 4*49)
#define ACT 196

__global__ __launch_bounds__(BLOCK) void pooler_kernel(
    const float* __restrict__ f0, const float* __restrict__ f1,
    const float* __restrict__ f2, const float* __restrict__ f3,
    const float* __restrict__ boxes, const int* __restrict__ img_ids,
    float* __restrict__ out)
{
    const int n   = blockIdx.x;
    const int tid = threadIdx.x;

    __shared__ int   s_ro0[P], s_ro1[P];   // y0*W, y1*W
    __shared__ int   s_x0[P],  s_x1[P];
    __shared__ float s_ay0[P], s_ay1[P];   // 0.25 * vy * {hy, ly}
    __shared__ float s_ax0[P], s_ax1[P];   // vx * {hx, lx}
    __shared__ const float* s_base;
    __shared__ int s_HW;

    // ---- per-box geometry (parallel: x by tid 0..13, y by tid 16..29, scalars by 32) ----
    {
        const float bx1 = boxes[4*n+0], by1 = boxes[4*n+1];
        const float bx2 = boxes[4*n+2], by2 = boxes[4*n+3];
        const float sq  = sqrtf((bx2 - bx1) * (by2 - by1));
        float lf = floorf(4.0f + log2f(sq / 224.0f + 1e-6f));
        lf = fminf(fmaxf(lf, 2.0f), 5.0f);
        const int lvl = (int)lf - 2;

        int H, W; float scale; const float* fp;
        switch (lvl) {
            case 0:  H = 200; W = 200; scale = 0.25f;    fp = f0; break;
            case 1:  H = 100; W = 100; scale = 0.125f;   fp = f1; break;
            case 2:  H = 50;  W = 50;  scale = 0.0625f;  fp = f2; break;
            default: H = 25;  W = 25;  scale = 0.03125f; fp = f3; break;
        }
        const int HW = H * W;

        const float rx1 = bx1 * scale, ry1 = by1 * scale;
        const float roi_w = fmaxf(bx2 * scale - rx1, 1.0f);
        const float roi_h = fmaxf(by2 * scale - ry1, 1.0f);
        const float bw = roi_w * (1.0f / 7.0f);
        const float bh = roi_h * (1.0f / 7.0f);

        if (tid < P) {
            const int i = tid, p = i >> 1, r = i & 1;
            const float xg = rx1 + (float)p * bw + ((float)r + 0.5f) * bw * 0.5f;
            const float vx = (xg >= -1.0f && xg <= (float)W) ? 1.0f : 0.0f;
            float x = fminf(fmaxf(xg, 0.0f), (float)(W - 1));
            const int x0 = (int)x;                   // x>=0: trunc == floor
            s_x0[i] = x0;
            s_x1[i] = min(x0 + 1, W - 1);
            const float lx = x - (float)x0;
            s_ax0[i] = vx * (1.0f - lx);
            s_ax1[i] = vx * lx;
        } else if (tid >= 16 && tid < 16 + P) {
            const int i = tid - 16, p = i >> 1, r = i & 1;
            const float yg = ry1 + (float)p * bh + ((float)r + 0.5f) * bh * 0.5f;
            const float vy = (yg >= -1.0f && yg <= (float)H) ? 0.25f : 0.0f;  // fold 0.25
            float y = fminf(fmaxf(yg, 0.0f), (float)(H - 1));
            const int y0 = (int)y;
            s_ro0[i] = y0 * W;
            s_ro1[i] = min(y0 + 1, H - 1) * W;
            const float ly = y - (float)y0;
            s_ay0[i] = vy * (1.0f - ly);
            s_ay1[i] = vy * ly;
        } else if (tid == 32) {
            const int img = __ldg(img_ids + n);
            s_base = fp + (size_t)img * 256 * HW;
            s_HW   = HW;
        }
    }
    __syncthreads();

    if (tid >= ACT) return;

    // ---- hoist fixed-bin geometry into registers ----
    const int csub = tid / 49;          // 0..3
    const int bin  = tid - csub * 49;   // fixed for this thread
    const int ph = bin / 7, pw = bin - ph * 7;
    const int iyA = 2*ph, iyB = iyA + 1;
    const int ixA = 2*pw, ixB = ixA + 1;

    const int r0 = s_ro0[iyA], r1 = s_ro1[iyA];
    const int r2 = s_ro0[iyB], r3 = s_ro1[iyB];
    const int c0 = s_x0[ixA],  c1 = s_x1[ixA];
    const int c2 = s_x0[ixB],  c3 = s_x1[ixB];
    const float a0 = s_ay0[iyA], a1 = s_ay1[iyA];
    const float a2 = s_ay0[iyB], a3 = s_ay1[iyB];
    const float b0 = s_ax0[ixA], b1 = s_ax1[ixA];
    const float b2 = s_ax0[ixB], b3 = s_ax1[ixB];

    // precombined element offsets (16 ints)
    const int i00 = r0+c0, i01 = r0+c1, i02 = r0+c2, i03 = r0+c3;
    const int i10 = r1+c0, i11 = r1+c1, i12 = r1+c2, i13 = r1+c3;
    const int i20 = r2+c0, i21 = r2+c1, i22 = r2+c2, i23 = r2+c3;
    const int i30 = r3+c0, i31 = r3+c1, i32 = r3+c2, i33 = r3+c3;

    const int HW = s_HW;
    const size_t chStep = (size_t)4 * HW;
    const float* fcA = s_base + (size_t)csub * HW;        // channels csub + 4i
    const float* fcB = fcA + (size_t)128 * HW;            // channels csub+128 + 4i
    float* outp = out + (size_t)n * 12544 + tid;          // idx = csub*49+bin = tid

    #pragma unroll 1
    for (int i = 0; i < 32; ++i) {
        // channel A: 16 independent loads
        const float pA00 = __ldg(fcA + i00), pA01 = __ldg(fcA + i01);
        const float pA02 = __ldg(fcA + i02), pA03 = __ldg(fcA + i03);
        const float pA10 = __ldg(fcA + i10), pA11 = __ldg(fcA + i11);
        const float pA12 = __ldg(fcA + i12), pA13 = __ldg(fcA + i13);
        const float pA20 = __ldg(fcA + i20), pA21 = __ldg(fcA + i21);
        const float pA22 = __ldg(fcA + i22), pA23 = __ldg(fcA + i23);
        const float pA30 = __ldg(fcA + i30), pA31 = __ldg(fcA + i31);
        const float pA32 = __ldg(fcA + i32), pA33 = __ldg(fcA + i33);
        // channel B: 16 independent loads
        const float pB00 = __ldg(fcB + i00), pB01 = __ldg(fcB + i01);
        const float pB02 = __ldg(fcB + i02), pB03 = __ldg(fcB + i03);
        const float pB10 = __ldg(fcB + i10), pB11 = __ldg(fcB + i11);
        const float pB12 = __ldg(fcB + i12), pB13 = __ldg(fcB + i13);
        const float pB20 = __ldg(fcB + i20), pB21 = __ldg(fcB + i21);
        const float pB22 = __ldg(fcB + i22), pB23 = __ldg(fcB + i23);
        const float pB30 = __ldg(fcB + i30), pB31 = __ldg(fcB + i31);
        const float pB32 = __ldg(fcB + i32), pB33 = __ldg(fcB + i33);

        // separable reduce: per y-row x-sum, then y-combine
        float sA0 = b0*pA00 + b1*pA01 + b2*pA02 + b3*pA03;
        float sA1 = b0*pA10 + b1*pA11 + b2*pA12 + b3*pA13;
        float sA2 = b0*pA20 + b1*pA21 + b2*pA22 + b3*pA23;
        float sA3 = b0*pA30 + b1*pA31 + b2*pA32 + b3*pA33;
        const float accA = a0*sA0 + a1*sA1 + a2*sA2 + a3*sA3;

        float sB0 = b0*pB00 + b1*pB01 + b2*pB02 + b3*pB03;
        float sB1 = b0*pB10 + b1*pB11 + b2*pB12 + b3*pB13;
        float sB2 = b0*pB20 + b1*pB21 + b2*pB22 + b3*pB23;
        float sB3 = b0*pB30 + b1*pB31 + b2*pB32 + b3*pB33;
        const float accB = a0*sB0 + a1*sB1 + a2*sB2 + a3*sB3;

        outp[0]    = accA;   // (c, bin)
        outp[6272] = accB;   // (c+128, bin)

        fcA += chStep;
        fcB += chStep;
        outp += ACT;
    }
}

extern "C" void kernel_launch(void* const* d_in, const int* in_sizes, int n_in,
                              void* d_out, int out_size)
{
    const float* f0    = (const float*)d_in[0];
    const float* f1    = (const float*)d_in[1];
    const float* f2    = (const float*)d_in[2];
    const float* f3    = (const float*)d_in[3];
    const float* boxes = (const float*)d_in[4];
    const int*   imgs  = (const int*)d_in[5];
    float* out = (float*)d_out;

    const int N = in_sizes[4] / 4;   // 1000 boxes
    pooler_kernel<<<N, BLOCK>>>(f0, f1, f2, f3, boxes, imgs, out);
}

// round 8
// speedup vs baseline: 5.7234x; 2.2552x over previous
#include <cuda_runtime.h>

// FPN Pooler: multi-level ROIAlign, direct scattered-gather with
// fixed-bin-per-thread geometry hoisting. Occupancy-tuned (5 blocks/SM),
// small blocks (64 channels) for wave-tail smoothing.
// feats NCHW f32: f0 [2,256,200,200], f1 [2,256,100,100], f2 [2,256,50,50], f3 [2,256,25,25]
// boxes [1000,4], img_ids [1000] -> out [1000,256,7,7] f32

#define P 14           // OUT*SR samples per axis
#define BLOCK 224      // 7 warps; 196 active threads (196 = 4*49)
#define ACT 196
#define QCH 64         // channels per block (quarter)
#define ITERS 16       // QCH / 4 channel-substreams

__global__ __launch_bounds__(BLOCK, 5) void pooler_kernel(
    const float* __restrict__ f0, const float* __restrict__ f1,
    const float* __restrict__ f2, const float* __restrict__ f3,
    const float* __restrict__ boxes, const int* __restrict__ img_ids,
    float* __restrict__ out)
{
    const int bx  = blockIdx.x;
    const int n   = bx >> 2;
    const int q   = bx & 3;           // channel quarter
    const int tid = threadIdx.x;

    __shared__ int   s_ro0[P], s_ro1[P];   // y0*W, y1*W
    __shared__ int   s_x0[P],  s_x1[P];
    __shared__ float s_ay0[P], s_ay1[P];   // 0.25 * vy * {hy, ly}
    __shared__ float s_ax0[P], s_ax1[P];   // vx * {hx, lx}
    __shared__ const float* s_base;
    __shared__ int s_HW;

    // ---- per-box geometry (x by tid 0..13, y by tid 16..29, scalars by 32) ----
    {
        const float bx1 = boxes[4*n+0], by1 = boxes[4*n+1];
        const float bx2 = boxes[4*n+2], by2 = boxes[4*n+3];
        const float sq  = sqrtf((bx2 - bx1) * (by2 - by1));
        float lf = floorf(4.0f + log2f(sq / 224.0f + 1e-6f));
        lf = fminf(fmaxf(lf, 2.0f), 5.0f);
        const int lvl = (int)lf - 2;

        int H, W; float scale; const float* fp;
        switch (lvl) {
            case 0:  H = 200; W = 200; scale = 0.25f;    fp = f0; break;
            case 1:  H = 100; W = 100; scale = 0.125f;   fp = f1; break;
            case 2:  H = 50;  W = 50;  scale = 0.0625f;  fp = f2; break;
            default: H = 25;  W = 25;  scale = 0.03125f; fp = f3; break;
        }
        const int HW = H * W;

        const float rx1 = bx1 * scale, ry1 = by1 * scale;
        const float roi_w = fmaxf(bx2 * scale - rx1, 1.0f);
        const float roi_h = fmaxf(by2 * scale - ry1, 1.0f);
        const float bw = roi_w * (1.0f / 7.0f);
        const float bh = roi_h * (1.0f / 7.0f);

        if (tid < P) {
            const int i = tid, p = i >> 1, r = i & 1;
            const float xg = rx1 + (float)p * bw + ((float)r + 0.5f) * bw * 0.5f;
            const float vx = (xg >= -1.0f && xg <= (float)W) ? 1.0f : 0.0f;
            float x = fminf(fmaxf(xg, 0.0f), (float)(W - 1));
            const int x0 = (int)x;                 // x>=0: trunc == floor
            s_x0[i] = x0;
            s_x1[i] = min(x0 + 1, W - 1);
            const float lx = x - (float)x0;
            s_ax0[i] = vx * (1.0f - lx);
            s_ax1[i] = vx * lx;
        } else if (tid >= 16 && tid < 16 + P) {
            const int i = tid - 16, p = i >> 1, r = i & 1;
            const float yg = ry1 + (float)p * bh + ((float)r + 0.5f) * bh * 0.5f;
            const float vy = (yg >= -1.0f && yg <= (float)H) ? 0.25f : 0.0f;  // fold mean
            float y = fminf(fmaxf(yg, 0.0f), (float)(H - 1));
            const int y0 = (int)y;
            s_ro0[i] = y0 * W;
            s_ro1[i] = min(y0 + 1, H - 1) * W;
            const float ly = y - (float)y0;
            s_ay0[i] = vy * (1.0f - ly);
            s_ay1[i] = vy * ly;
        } else if (tid == 32) {
            const int img = __ldg(img_ids + n);
            s_base = fp + (size_t)img * 256 * HW;
            s_HW   = HW;
        }
    }
    __syncthreads();

    if (tid >= ACT) return;

    // ---- fixed-bin geometry in registers (once per block) ----
    const int csub = tid / 49;          // 0..3
    const int bin  = tid - csub * 49;
    const int ph = bin / 7, pw = bin - ph * 7;
    const int iyA = 2*ph, iyB = iyA + 1;
    const int ixA = 2*pw, ixB = ixA + 1;

    const int r0 = s_ro0[iyA], r1 = s_ro1[iyA];
    const int r2 = s_ro0[iyB], r3 = s_ro1[iyB];
    const int c0 = s_x0[ixA],  c1 = s_x1[ixA];
    const int c2 = s_x0[ixB],  c3 = s_x1[ixB];
    const float a0 = s_ay0[iyA], a1 = s_ay1[iyA];
    const float a2 = s_ay0[iyB], a3 = s_ay1[iyB];
    const float b0 = s_ax0[ixA], b1 = s_ax1[ixA];
    const float b2 = s_ax0[ixB], b3 = s_ax1[ixB];

    const int i00 = r0+c0, i01 = r0+c1, i02 = r0+c2, i03 = r0+c3;
    const int i10 = r1+c0, i11 = r1+c1, i12 = r1+c2, i13 = r1+c3;
    const int i20 = r2+c0, i21 = r2+c1, i22 = r2+c2, i23 = r2+c3;
    const int i30 = r3+c0, i31 = r3+c1, i32 = r3+c2, i33 = r3+c3;

    const int HW = s_HW;
    const size_t chStep = (size_t)4 * HW;
    // channel = q*64 + csub + 4*i
    const float* fc = s_base + (size_t)(q * QCH + csub) * HW;
    float* outp = out + (size_t)n * 12544 + (size_t)q * (QCH * 49) + tid;

    #pragma unroll 1
    for (int i = 0; i < ITERS; ++i) {
        const float p00 = __ldg(fc + i00), p01 = __ldg(fc + i01);
        const float p02 = __ldg(fc + i02), p03 = __ldg(fc + i03);
        const float p10 = __ldg(fc + i10), p11 = __ldg(fc + i11);
        const float p12 = __ldg(fc + i12), p13 = __ldg(fc + i13);
        const float p20 = __ldg(fc + i20), p21 = __ldg(fc + i21);
        const float p22 = __ldg(fc + i22), p23 = __ldg(fc + i23);
        const float p30 = __ldg(fc + i30), p31 = __ldg(fc + i31);
        const float p32 = __ldg(fc + i32), p33 = __ldg(fc + i33);

        float s0 = b0*p00 + b1*p01 + b2*p02 + b3*p03;
        float s1 = b0*p10 + b1*p11 + b2*p12 + b3*p13;
        float s2 = b0*p20 + b1*p21 + b2*p22 + b3*p23;
        float s3 = b0*p30 + b1*p31 + b2*p32 + b3*p33;
        const float acc = a0*s0 + a1*s1 + a2*s2 + a3*s3;

        *outp = acc;

        fc += chStep;
        outp += ACT;
    }
}

extern "C" void kernel_launch(void* const* d_in, const int* in_sizes, int n_in,
                              void* d_out, int out_size)
{
    const float* f0    = (const float*)d_in[0];
    const float* f1    = (const float*)d_in[1];
    const float* f2    = (const float*)d_in[2];
    const float* f3    = (const float*)d_in[3];
    const float* boxes = (const float*)d_in[4];
    const int*   imgs  = (const int*)d_in[5];
    float* out = (float*)d_out;

    const int N = in_sizes[4] / 4;   // 1000 boxes
    pooler_kernel<<<N * 4, BLOCK>>>(f0, f1, f2, f3, boxes, imgs, out);
}